// round 1
// baseline (speedup 1.0000x reference)
#include <cuda_runtime.h>

#define TS 2048       // sequence length
#define DM 1024       // d_model
#define NH 16         // heads
#define HD 64         // head dim
#define NB 2          // batch
#define MROWS (NB*TS) // 4096

// Scratch (no cudaMalloc allowed): Q/K/V in [B,H,S,HD], attn out in [B,S,D]
static __device__ float g_q[NB*NH*TS*HD];
static __device__ float g_k[NB*NH*TS*HD];
static __device__ float g_v[NB*NH*TS*HD];
static __device__ float g_att[NB*TS*DM];

// ---------------------------------------------------------------------------
// GEMM 1: qkv = x @ w_qkv + b_qkv, scattered into g_q/g_k/g_v [B,H,S,HD]
// 128x128 tile, BK=8, 256 threads, 8x8 per thread (2x2 quads of 4x4)
// ---------------------------------------------------------------------------
__global__ __launch_bounds__(256)
void qkv_gemm_kernel(const float* __restrict__ A,
                     const float* __restrict__ B,
                     const float* __restrict__ bias)
{
    const int K = DM, N = 3*DM;
    __shared__ float As[8][128];   // transposed: As[k][m]
    __shared__ float Bs[8][128];   // Bs[k][n]
    const int tid = threadIdx.x;
    const int m0 = blockIdx.y * 128;
    const int n0 = blockIdx.x * 128;
    const int arow = tid >> 1;
    const int acol = (tid & 1) << 2;
    const int brow = tid >> 5;
    const int bcol = (tid & 31) << 2;
    const int ty = tid >> 4;
    const int tx = tid & 15;

    float acc[2][2][4][4];
#pragma unroll
    for (int a=0;a<2;a++)
#pragma unroll
      for (int b=0;b<2;b++)
#pragma unroll
        for (int i=0;i<4;i++)
#pragma unroll
          for (int j=0;j<4;j++) acc[a][b][i][j]=0.f;

    const float* Ap = A + (size_t)(m0 + arow) * K + acol;
    const float* Bp = B + (size_t)brow * N + n0 + bcol;

    for (int k0 = 0; k0 < K; k0 += 8) {
        float4 av = *(const float4*)Ap;
        float4 bv = *(const float4*)Bp;
        As[acol+0][arow] = av.x;
        As[acol+1][arow] = av.y;
        As[acol+2][arow] = av.z;
        As[acol+3][arow] = av.w;
        *(float4*)&Bs[brow][bcol] = bv;
        __syncthreads();
#pragma unroll
        for (int k = 0; k < 8; ++k) {
            float a0[4],a1[4],b0[4],b1[4];
            *(float4*)a0 = *(const float4*)&As[k][ty*4];
            *(float4*)a1 = *(const float4*)&As[k][ty*4+64];
            *(float4*)b0 = *(const float4*)&Bs[k][tx*4];
            *(float4*)b1 = *(const float4*)&Bs[k][tx*4+64];
#pragma unroll
            for (int i=0;i<4;i++) {
#pragma unroll
              for (int j=0;j<4;j++) {
                acc[0][0][i][j] += a0[i]*b0[j];
                acc[0][1][i][j] += a0[i]*b1[j];
                acc[1][0][i][j] += a1[i]*b0[j];
                acc[1][1][i][j] += a1[i]*b1[j];
              }
            }
        }
        __syncthreads();
        Ap += 8;
        Bp += (size_t)8 * N;
    }

    // Epilogue: scatter into [B,H,S,HD] buffers.
#pragma unroll
    for (int cq=0;cq<2;cq++) {
        const int n = n0 + cq*64 + tx*4;
        const int which = n >> 10;         // 0=Q,1=K,2=V
        const int rem = n & 1023;
        const int h = rem >> 6;
        const int hd = rem & 63;
        float* dst = (which==0) ? g_q : (which==1) ? g_k : g_v;
        const float4 bb = *(const float4*)&bias[n];
#pragma unroll
        for (int rq=0;rq<2;rq++) {
#pragma unroll
            for (int i=0;i<4;i++) {
                const int m = m0 + rq*64 + ty*4 + i;
                const int bi = m >> 11;     // / TS
                const int s = m & (TS-1);
                float4 v;
                v.x = acc[rq][cq][i][0] + bb.x;
                v.y = acc[rq][cq][i][1] + bb.y;
                v.z = acc[rq][cq][i][2] + bb.z;
                v.w = acc[rq][cq][i][3] + bb.w;
                *(float4*)&dst[(((bi*NH + h)*TS + s)*HD) + hd] = v;
            }
        }
    }
}

// ---------------------------------------------------------------------------
// Flash attention: one CTA per (b,h, 128-row q tile). Bc = 64. fp32.
// Thread layout 16(ty) x 16(tx): score tile rows ty*8+i, cols tx*4+j.
// Smem: Qt[64][128] (d,r), Kt[64][64] (d,c), Vs[64][64] (kc,hd), Ps[128][68]
// ---------------------------------------------------------------------------
#define BR 128
#define BC 64
#define PS_PITCH 68
#define ATT_SMEM_FLOATS (64*BR + 64*BC + BC*HD + BR*PS_PITCH)

__global__ __launch_bounds__(256)
void attn_kernel()
{
    extern __shared__ float sm[];
    float* Qt = sm;                       // [d][r], pitch BR
    float* Kt = Qt + 64*BR;               // [d][c], pitch BC
    float* Vs = Kt + 64*BC;               // [kc][hd], pitch HD
    float* Ps = Vs + BC*HD;               // [r][kc], pitch PS_PITCH

    const int tid = threadIdx.x;
    const int ty = tid >> 4;
    const int tx = tid & 15;
    const int bh = blockIdx.y;            // b*NH + h
    const int q0 = blockIdx.x * BR;

    const float* Qg = g_q + (size_t)bh * TS * HD + (size_t)q0 * HD;
    const float* Kg = g_k + (size_t)bh * TS * HD;
    const float* Vg = g_v + (size_t)bh * TS * HD;

    const float qscale = 0.125f;          // 1/sqrt(64)

    // Load Q tile transposed + pre-scaled
    for (int idx = tid; idx < BR*16; idx += 256) {
        const int r = idx >> 4;
        const int c4 = (idx & 15) << 2;
        float4 f = *(const float4*)(Qg + r*HD + c4);
        Qt[(c4+0)*BR + r] = f.x * qscale;
        Qt[(c4+1)*BR + r] = f.y * qscale;
        Qt[(c4+2)*BR + r] = f.z * qscale;
        Qt[(c4+3)*BR + r] = f.w * qscale;
    }

    float m_i[8], l_i[8], oacc[8][4];
#pragma unroll
    for (int i=0;i<8;i++) {
        m_i[i] = -1e30f;
        l_i[i] = 0.f;
#pragma unroll
        for (int j=0;j<4;j++) oacc[i][j] = 0.f;
    }

    for (int kt = 0; kt < TS/BC; ++kt) {
        __syncthreads();   // prior-iter readers of Kt/Vs/Ps done; Qt ready (iter 0)
        const float* Kgt = Kg + (size_t)kt * BC * HD;
        const float* Vgt = Vg + (size_t)kt * BC * HD;
        for (int idx = tid; idx < BC*16; idx += 256) {
            const int r = idx >> 4;
            const int c4 = (idx & 15) << 2;
            float4 fk = *(const float4*)(Kgt + r*HD + c4);
            Kt[(c4+0)*BC + r] = fk.x;
            Kt[(c4+1)*BC + r] = fk.y;
            Kt[(c4+2)*BC + r] = fk.z;
            Kt[(c4+3)*BC + r] = fk.w;
            *(float4*)&Vs[r*HD + c4] = *(const float4*)(Vgt + r*HD + c4);
        }
        __syncthreads();

        // S = (Q*scale) @ K^T
        float sacc[8][4];
#pragma unroll
        for (int i=0;i<8;i++)
#pragma unroll
          for (int j=0;j<4;j++) sacc[i][j]=0.f;

#pragma unroll 16
        for (int d = 0; d < HD; ++d) {
            float qv[8], kv[4];
            *(float4*)&qv[0] = *(const float4*)&Qt[d*BR + ty*8];
            *(float4*)&qv[4] = *(const float4*)&Qt[d*BR + ty*8 + 4];
            *(float4*)&kv[0] = *(const float4*)&Kt[d*BC + tx*4];
#pragma unroll
            for (int i=0;i<8;i++)
#pragma unroll
              for (int j=0;j<4;j++) sacc[i][j] += qv[i]*kv[j];
        }

        // Online softmax per row (rows split across 16 tx lanes, 4 cols each)
#pragma unroll
        for (int i=0;i<8;i++) {
            float rmax = fmaxf(fmaxf(sacc[i][0], sacc[i][1]),
                               fmaxf(sacc[i][2], sacc[i][3]));
#pragma unroll
            for (int msk=1; msk<16; msk<<=1)
                rmax = fmaxf(rmax, __shfl_xor_sync(0xffffffffu, rmax, msk));
            const float mnew = fmaxf(m_i[i], rmax);
            float p0 = __expf(sacc[i][0] - mnew);
            float p1 = __expf(sacc[i][1] - mnew);
            float p2 = __expf(sacc[i][2] - mnew);
            float p3 = __expf(sacc[i][3] - mnew);
            float rsum = p0 + p1 + p2 + p3;
#pragma unroll
            for (int msk=1; msk<16; msk<<=1)
                rsum += __shfl_xor_sync(0xffffffffu, rsum, msk);
            const float alpha = __expf(m_i[i] - mnew);
            l_i[i] = l_i[i]*alpha + rsum;
            m_i[i] = mnew;
#pragma unroll
            for (int j=0;j<4;j++) oacc[i][j] *= alpha;
            float4 pv; pv.x=p0; pv.y=p1; pv.z=p2; pv.w=p3;
            *(float4*)&Ps[(ty*8+i)*PS_PITCH + tx*4] = pv;
        }
        __syncthreads();

        // O += P @ V
#pragma unroll 8
        for (int kc = 0; kc < BC; ++kc) {
            float vv[4];
            *(float4*)vv = *(const float4*)&Vs[kc*HD + tx*4];
#pragma unroll
            for (int i=0;i<8;i++) {
                const float p = Ps[(ty*8+i)*PS_PITCH + kc];
#pragma unroll
                for (int j=0;j<4;j++) oacc[i][j] += p * vv[j];
            }
        }
    }

    // Write O / l to g_att in [B,S,D] layout
    const int b = bh / NH;
    const int h = bh % NH;
#pragma unroll
    for (int i=0;i<8;i++) {
        const int r = ty*8 + i;
        const float inv = 1.0f / l_i[i];
        float4 o;
        o.x = oacc[i][0]*inv;
        o.y = oacc[i][1]*inv;
        o.z = oacc[i][2]*inv;
        o.w = oacc[i][3]*inv;
        *(float4*)&g_att[((size_t)(b*TS + q0 + r))*DM + h*HD + tx*4] = o;
    }
}

// ---------------------------------------------------------------------------
// GEMM 3: out = g_att @ w_out + b_out -> d_out [B*S, D]
// ---------------------------------------------------------------------------
__global__ __launch_bounds__(256)
void out_gemm_kernel(const float* __restrict__ B,
                     const float* __restrict__ bias,
                     float* __restrict__ C)
{
    const int K = DM, N = DM;
    const float* A = g_att;
    __shared__ float As[8][128];
    __shared__ float Bs[8][128];
    const int tid = threadIdx.x;
    const int m0 = blockIdx.y * 128;
    const int n0 = blockIdx.x * 128;
    const int arow = tid >> 1;
    const int acol = (tid & 1) << 2;
    const int brow = tid >> 5;
    const int bcol = (tid & 31) << 2;
    const int ty = tid >> 4;
    const int tx = tid & 15;

    float acc[2][2][4][4];
#pragma unroll
    for (int a=0;a<2;a++)
#pragma unroll
      for (int b=0;b<2;b++)
#pragma unroll
        for (int i=0;i<4;i++)
#pragma unroll
          for (int j=0;j<4;j++) acc[a][b][i][j]=0.f;

    const float* Ap = A + (size_t)(m0 + arow) * K + acol;
    const float* Bp = B + (size_t)brow * N + n0 + bcol;

    for (int k0 = 0; k0 < K; k0 += 8) {
        float4 av = *(const float4*)Ap;
        float4 bv = *(const float4*)Bp;
        As[acol+0][arow] = av.x;
        As[acol+1][arow] = av.y;
        As[acol+2][arow] = av.z;
        As[acol+3][arow] = av.w;
        *(float4*)&Bs[brow][bcol] = bv;
        __syncthreads();
#pragma unroll
        for (int k = 0; k < 8; ++k) {
            float a0[4],a1[4],b0[4],b1[4];
            *(float4*)a0 = *(const float4*)&As[k][ty*4];
            *(float4*)a1 = *(const float4*)&As[k][ty*4+64];
            *(float4*)b0 = *(const float4*)&Bs[k][tx*4];
            *(float4*)b1 = *(const float4*)&Bs[k][tx*4+64];
#pragma unroll
            for (int i=0;i<4;i++) {
#pragma unroll
              for (int j=0;j<4;j++) {
                acc[0][0][i][j] += a0[i]*b0[j];
                acc[0][1][i][j] += a0[i]*b1[j];
                acc[1][0][i][j] += a1[i]*b0[j];
                acc[1][1][i][j] += a1[i]*b1[j];
              }
            }
        }
        __syncthreads();
        Ap += 8;
        Bp += (size_t)8 * N;
    }

#pragma unroll
    for (int cq=0;cq<2;cq++) {
        const int n = n0 + cq*64 + tx*4;
        const float4 bb = *(const float4*)&bias[n];
#pragma unroll
        for (int rq=0;rq<2;rq++) {
#pragma unroll
            for (int i=0;i<4;i++) {
                const int m = m0 + rq*64 + ty*4 + i;
                float4 v;
                v.x = acc[rq][cq][i][0] + bb.x;
                v.y = acc[rq][cq][i][1] + bb.y;
                v.z = acc[rq][cq][i][2] + bb.z;
                v.w = acc[rq][cq][i][3] + bb.w;
                *(float4*)&C[(size_t)m*N + n] = v;
            }
        }
    }
}

// ---------------------------------------------------------------------------
extern "C" void kernel_launch(void* const* d_in, const int* in_sizes, int n_in,
                              void* d_out, int out_size)
{
    const float* x     = (const float*)d_in[0];
    const float* w_qkv = (const float*)d_in[1];
    const float* b_qkv = (const float*)d_in[2];
    const float* w_out = (const float*)d_in[3];
    const float* b_out = (const float*)d_in[4];
    float* out = (float*)d_out;

    const int att_smem = ATT_SMEM_FLOATS * (int)sizeof(float);  // 100,352 B
    cudaFuncSetAttribute(attn_kernel,
                         cudaFuncAttributeMaxDynamicSharedMemorySize, att_smem);

    qkv_gemm_kernel<<<dim3(3*DM/128, MROWS/128), 256>>>(x, w_qkv, b_qkv);
    attn_kernel<<<dim3(TS/BR, NB*NH), 256, att_smem>>>();
    out_gemm_kernel<<<dim3(DM/128, MROWS/128), 256>>>(w_out, b_out, out);
}

// round 3
// speedup vs baseline: 1.4112x; 1.4112x over previous
#include <cuda_runtime.h>
#include <cuda_bf16.h>
#include <cstdint>

#define TS 2048       // sequence length
#define DM 1024       // d_model
#define NH 16         // heads
#define HD 64         // head dim
#define NB 2          // batch
#define MROWS (NB*TS) // 4096
#define GK DM         // reduction dim for both GEMMs
#define KC 64         // bf16 cols per K-chunk (128 bytes = SW128 row)
#define NCH (GK/KC)   // 16 chunks

// ---------------- scratch (no cudaMalloc allowed) ----------------
static __device__ __align__(256) float g_q[NB*NH*TS*HD];
static __device__ __align__(256) float g_k[NB*NH*TS*HD];
static __device__ __align__(256) float g_v[NB*NH*TS*HD];
static __device__ __align__(256) __nv_bfloat16 g_xh[MROWS*DM],  g_xl[MROWS*DM];   // x split
static __device__ __align__(256) __nv_bfloat16 g_wqh[3*DM*DM],  g_wql[3*DM*DM];   // w_qkv^T split [3D, D]
static __device__ __align__(256) __nv_bfloat16 g_woh[DM*DM],    g_wol[DM*DM];     // w_out^T split [D, D]
static __device__ __align__(256) __nv_bfloat16 g_ah[MROWS*DM],  g_al[MROWS*DM];   // attn output split

// ---------------- helpers ----------------
__device__ __forceinline__ uint32_t smem_u32(const void* p) {
    uint32_t a;
    asm("{ .reg .u64 t; cvta.to.shared.u64 t, %1; cvt.u32.u64 %0, t; }" : "=r"(a) : "l"(p));
    return a;
}
__device__ __forceinline__ void ldsm4(uint32_t* d, uint32_t addr) {
    asm volatile("ldmatrix.sync.aligned.m8n8.x4.shared.b16 {%0,%1,%2,%3}, [%4];"
        : "=r"(d[0]), "=r"(d[1]), "=r"(d[2]), "=r"(d[3]) : "r"(addr));
}
__device__ __forceinline__ void mma16816(float* c, const uint32_t* a, const uint32_t* b) {
    asm volatile("mma.sync.aligned.m16n8k16.row.col.f32.bf16.bf16.f32 "
        "{%0,%1,%2,%3}, {%4,%5,%6,%7}, {%8,%9}, {%0,%1,%2,%3};"
        : "+f"(c[0]), "+f"(c[1]), "+f"(c[2]), "+f"(c[3])
        : "r"(a[0]), "r"(a[1]), "r"(a[2]), "r"(a[3]), "r"(b[0]), "r"(b[1]));
}
__device__ __forceinline__ void cpasync16(uint32_t dst, const void* src) {
    asm volatile("cp.async.cg.shared.global [%0], [%1], 16;" :: "r"(dst), "l"(src));
}
#define CP_COMMIT() asm volatile("cp.async.commit_group;" ::: "memory")
#define CP_WAIT0()  asm volatile("cp.async.wait_group 0;" ::: "memory")

// ---------------- conversion kernels ----------------
__global__ __launch_bounds__(256)
void split_kernel(const float* __restrict__ s, __nv_bfloat16* __restrict__ h,
                  __nv_bfloat16* __restrict__ l)
{
    int i = (blockIdx.x * 256 + threadIdx.x) * 4;
    float4 v = *(const float4*)(s + i);
    float a[4] = {v.x, v.y, v.z, v.w};
    __nv_bfloat16 hh[4], ll[4];
#pragma unroll
    for (int j = 0; j < 4; j++) {
        hh[j] = __float2bfloat16(a[j]);
        ll[j] = __float2bfloat16(a[j] - __bfloat162float(hh[j]));
    }
    *(__nv_bfloat162*)(h + i)     = __nv_bfloat162(hh[0], hh[1]);
    *(__nv_bfloat162*)(h + i + 2) = __nv_bfloat162(hh[2], hh[3]);
    *(__nv_bfloat162*)(l + i)     = __nv_bfloat162(ll[0], ll[1]);
    *(__nv_bfloat162*)(l + i + 2) = __nv_bfloat162(ll[2], ll[3]);
}

// transpose + split: src[K,N] fp32 -> hT/lT[N,K] bf16
__global__ __launch_bounds__(256)
void tsplit_kernel(const float* __restrict__ s, __nv_bfloat16* __restrict__ hT,
                   __nv_bfloat16* __restrict__ lT, int K, int N)
{
    __shared__ float t[32][33];
    const int n0 = blockIdx.x * 32, k0 = blockIdx.y * 32;
    const int tx = threadIdx.x, ty = threadIdx.y;   // (32, 8)
#pragma unroll
    for (int j = 0; j < 4; j++)
        t[ty + j*8][tx] = s[(size_t)(k0 + ty + j*8) * N + n0 + tx];
    __syncthreads();
#pragma unroll
    for (int j = 0; j < 4; j++) {
        float v = t[tx][ty + j*8];
        __nv_bfloat16 h = __float2bfloat16(v);
        __nv_bfloat16 l = __float2bfloat16(v - __bfloat162float(h));
        size_t o = (size_t)(n0 + ty + j*8) * K + k0 + tx;
        hT[o] = h; lT[o] = l;
    }
}

// ---------------- split-bf16 mma.sync GEMM ----------------
// C[128,128] tile per CTA. A[M,K] hi/lo K-major, B[N,K] hi/lo K-major.
// EPI=0: bias + scatter to g_q/g_k/g_v ([B,H,S,HD]); EPI=1: bias + row-major C.
#define TILE_B 16384                  // 128 rows x 128 bytes
#define BUF_B  (4 * TILE_B)           // Ah, Al, Bh, Bl
#define GEMM_SMEM (2 * BUF_B)         // 131072 (double buffered)

template <int EPI>
__global__ __launch_bounds__(256)
void gemm_mma(const __nv_bfloat16* __restrict__ Ah,
              const __nv_bfloat16* __restrict__ Al,
              const __nv_bfloat16* __restrict__ Bh,
              const __nv_bfloat16* __restrict__ Bl,
              const float* __restrict__ bias,
              float* __restrict__ C, int Ncols)
{
    extern __shared__ __align__(128) char smc[];
    const uint32_t smb = smem_u32(smc);
    const int tid = threadIdx.x;
    const int lane = tid & 31, wid = tid >> 5;
    const int m0 = blockIdx.y * 128;
    const int n0 = blockIdx.x * 128;
    const int wm = (wid & 3) * 32;       // warp m-offset within tile
    const int wn = (wid >> 2) * 64;      // warp n-offset within tile

    float acc[2][8][4];
#pragma unroll
    for (int mf = 0; mf < 2; mf++)
#pragma unroll
        for (int nf = 0; nf < 8; nf++)
#pragma unroll
            for (int j = 0; j < 4; j++) acc[mf][nf][j] = 0.f;

    const __nv_bfloat16* srcs[4] = {Ah, Al, Bh, Bl};

    // ---- loader: one K-chunk (4 tiles of 128 rows x 64 bf16) via cp.async ----
    auto load_chunk = [&](int c, int stage) {
#pragma unroll
        for (int t = 0; t < 4; t++) {
            const int rowbase = (t < 2) ? m0 : n0;
            const __nv_bfloat16* g = srcs[t] + (size_t)rowbase * GK + c * KC;
            const uint32_t sbase = smb + stage * BUF_B + t * TILE_B;
#pragma unroll
            for (int i = 0; i < 4; i++) {
                const int idx = tid + i * 256;       // [0,1024)
                const int r = idx >> 3;
                const int c8 = (idx & 7) << 3;       // bf16 col (16B steps)
                uint32_t off = r * 128 + c8 * 2;
                uint32_t sw = off ^ ((off >> 3) & 0x70);
                cpasync16(sbase + sw, g + (size_t)r * GK + c8);
            }
        }
        CP_COMMIT();
    };

    load_chunk(0, 0);

    // per-thread ldmatrix row/koff (canonical row.col mapping, both K-major)
    const uint32_t a_row  = wm + (lane & 15);
    const uint32_t a_koff = (lane >> 4) * 16;                        // bytes
    const uint32_t b_row  = wn + ((lane >> 4) << 3) + (lane & 7);
    const uint32_t b_koff = ((lane >> 3) & 1) * 16;                  // bytes

    for (int c = 0; c < NCH; ++c) {
        const int st = c & 1;
        CP_WAIT0();
        __syncthreads();
        if (c + 1 < NCH) load_chunk(c + 1, st ^ 1);

        const uint32_t base = smb + st * BUF_B;
#pragma unroll
        for (int ks = 0; ks < 4; ks++) {
            const uint32_t kb = ks * 32;
            uint32_t ah[2][4], al[2][4], bh[4][4], bl[4][4];
#pragma unroll
            for (int mf = 0; mf < 2; mf++) {
                uint32_t off = (a_row + mf * 16) * 128 + kb + a_koff;
                uint32_t sw = off ^ ((off >> 3) & 0x70);
                ldsm4(ah[mf], base + sw);
                ldsm4(al[mf], base + TILE_B + sw);
            }
#pragma unroll
            for (int nf2 = 0; nf2 < 4; nf2++) {
                uint32_t off = (b_row + nf2 * 16) * 128 + kb + b_koff;
                uint32_t sw = off ^ ((off >> 3) & 0x70);
                ldsm4(bh[nf2], base + 2 * TILE_B + sw);
                ldsm4(bl[nf2], base + 3 * TILE_B + sw);
            }
#pragma unroll
            for (int mf = 0; mf < 2; mf++)
#pragma unroll
                for (int nf = 0; nf < 8; nf++) {
                    const uint32_t* bhp = &bh[nf >> 1][(nf & 1) * 2];
                    const uint32_t* blp = &bl[nf >> 1][(nf & 1) * 2];
                    mma16816(acc[mf][nf], ah[mf], bhp);   // hi*hi
                    mma16816(acc[mf][nf], ah[mf], blp);   // hi*lo
                    mma16816(acc[mf][nf], al[mf], bhp);   // lo*hi
                }
        }
    }

    // ---- epilogue: bias + store ----
#pragma unroll
    for (int mf = 0; mf < 2; mf++) {
#pragma unroll
        for (int nf = 0; nf < 8; nf++) {
            const int n = n0 + wn + nf * 8 + (lane & 3) * 2;
            const int row0 = m0 + wm + mf * 16 + (lane >> 2);
            const float2 bb = *(const float2*)&bias[n];
            if (EPI == 0) {
                const int which = n >> 10;           // 0=q,1=k,2=v
                const int h = (n >> 6) & 15;
                const int hd = n & 63;
                float* dstbuf = (which == 0) ? g_q : (which == 1) ? g_k : g_v;
#pragma unroll
                for (int rr = 0; rr < 2; rr++) {
                    const int row = row0 + rr * 8;
                    const int bi = row >> 11;        // / TS
                    const int s = row & (TS - 1);
                    float2 v;
                    v.x = acc[mf][nf][rr * 2 + 0] + bb.x;
                    v.y = acc[mf][nf][rr * 2 + 1] + bb.y;
                    *(float2*)&dstbuf[((size_t)(bi * NH + h) * TS + s) * HD + hd] = v;
                }
            } else {
#pragma unroll
                for (int rr = 0; rr < 2; rr++) {
                    const int row = row0 + rr * 8;
                    float2 v;
                    v.x = acc[mf][nf][rr * 2 + 0] + bb.x;
                    v.y = acc[mf][nf][rr * 2 + 1] + bb.y;
                    *(float2*)&C[(size_t)row * Ncols + n] = v;
                }
            }
        }
    }
}

// ---------------------------------------------------------------------------
// Flash attention (fp32) — writes split bf16 output for the out-projection
// ---------------------------------------------------------------------------
#define BR 128
#define BC 64
#define PS_PITCH 68
#define ATT_SMEM_FLOATS (64*BR + 64*BC + BC*HD + BR*PS_PITCH)

__global__ __launch_bounds__(256)
void attn_kernel()
{
    extern __shared__ float smf[];
    float* Qt = smf;
    float* Kt = Qt + 64*BR;
    float* Vs = Kt + 64*BC;
    float* Ps = Vs + BC*HD;

    const int tid = threadIdx.x;
    const int ty = tid >> 4;
    const int tx = tid & 15;
    const int bh = blockIdx.y;
    const int q0 = blockIdx.x * BR;

    const float* Qg = g_q + (size_t)bh * TS * HD + (size_t)q0 * HD;
    const float* Kg = g_k + (size_t)bh * TS * HD;
    const float* Vg = g_v + (size_t)bh * TS * HD;

    const float qscale = 0.125f;

    for (int idx = tid; idx < BR*16; idx += 256) {
        const int r = idx >> 4;
        const int c4 = (idx & 15) << 2;
        float4 f = *(const float4*)(Qg + r*HD + c4);
        Qt[(c4+0)*BR + r] = f.x * qscale;
        Qt[(c4+1)*BR + r] = f.y * qscale;
        Qt[(c4+2)*BR + r] = f.z * qscale;
        Qt[(c4+3)*BR + r] = f.w * qscale;
    }

    float m_i[8], l_i[8], oacc[8][4];
#pragma unroll
    for (int i=0;i<8;i++) {
        m_i[i] = -1e30f; l_i[i] = 0.f;
#pragma unroll
        for (int j=0;j<4;j++) oacc[i][j] = 0.f;
    }

    for (int kt = 0; kt < TS/BC; ++kt) {
        __syncthreads();
        const float* Kgt = Kg + (size_t)kt * BC * HD;
        const float* Vgt = Vg + (size_t)kt * BC * HD;
        for (int idx = tid; idx < BC*16; idx += 256) {
            const int r = idx >> 4;
            const int c4 = (idx & 15) << 2;
            float4 fk = *(const float4*)(Kgt + r*HD + c4);
            Kt[(c4+0)*BC + r] = fk.x;
            Kt[(c4+1)*BC + r] = fk.y;
            Kt[(c4+2)*BC + r] = fk.z;
            Kt[(c4+3)*BC + r] = fk.w;
            *(float4*)&Vs[r*HD + c4] = *(const float4*)(Vgt + r*HD + c4);
        }
        __syncthreads();

        float sacc[8][4];
#pragma unroll
        for (int i=0;i<8;i++)
#pragma unroll
          for (int j=0;j<4;j++) sacc[i][j]=0.f;

#pragma unroll 16
        for (int d = 0; d < HD; ++d) {
            float qv[8], kv[4];
            *(float4*)&qv[0] = *(const float4*)&Qt[d*BR + ty*8];
            *(float4*)&qv[4] = *(const float4*)&Qt[d*BR + ty*8 + 4];
            *(float4*)&kv[0] = *(const float4*)&Kt[d*BC + tx*4];
#pragma unroll
            for (int i=0;i<8;i++)
#pragma unroll
              for (int j=0;j<4;j++) sacc[i][j] += qv[i]*kv[j];
        }

#pragma unroll
        for (int i=0;i<8;i++) {
            float rmax = fmaxf(fmaxf(sacc[i][0], sacc[i][1]),
                               fmaxf(sacc[i][2], sacc[i][3]));
#pragma unroll
            for (int msk=1; msk<16; msk<<=1)
                rmax = fmaxf(rmax, __shfl_xor_sync(0xffffffffu, rmax, msk));
            const float mnew = fmaxf(m_i[i], rmax);
            float p0 = __expf(sacc[i][0] - mnew);
            float p1 = __expf(sacc[i][1] - mnew);
            float p2 = __expf(sacc[i][2] - mnew);
            float p3 = __expf(sacc[i][3] - mnew);
            float rsum = p0 + p1 + p2 + p3;
#pragma unroll
            for (int msk=1; msk<16; msk<<=1)
                rsum += __shfl_xor_sync(0xffffffffu, rsum, msk);
            const float alpha = __expf(m_i[i] - mnew);
            l_i[i] = l_i[i]*alpha + rsum;
            m_i[i] = mnew;
#pragma unroll
            for (int j=0;j<4;j++) oacc[i][j] *= alpha;
            float4 pv; pv.x=p0; pv.y=p1; pv.z=p2; pv.w=p3;
            *(float4*)&Ps[(ty*8+i)*PS_PITCH + tx*4] = pv;
        }
        __syncthreads();

#pragma unroll 8
        for (int kc = 0; kc < BC; ++kc) {
            float vv[4];
            *(float4*)vv = *(const float4*)&Vs[kc*HD + tx*4];
#pragma unroll
            for (int i=0;i<8;i++) {
                const float p = Ps[(ty*8+i)*PS_PITCH + kc];
#pragma unroll
                for (int j=0;j<4;j++) oacc[i][j] += p * vv[j];
            }
        }
    }

    // Write O split into bf16 hi/lo, [B*S, D] row-major
    const int b = bh / NH;
    const int h = bh % NH;
#pragma unroll
    for (int i=0;i<8;i++) {
        const int r = ty*8 + i;
        const float inv = 1.0f / l_i[i];
        float o[4];
#pragma unroll
        for (int j=0;j<4;j++) o[j] = oacc[i][j]*inv;
        __nv_bfloat16 oh[4], ol[4];
#pragma unroll
        for (int j=0;j<4;j++) {
            oh[j] = __float2bfloat16(o[j]);
            ol[j] = __float2bfloat16(o[j] - __bfloat162float(oh[j]));
        }
        const size_t base = ((size_t)(b*TS + q0 + r))*DM + h*HD + tx*4;
        *(__nv_bfloat162*)&g_ah[base]   = __nv_bfloat162(oh[0], oh[1]);
        *(__nv_bfloat162*)&g_ah[base+2] = __nv_bfloat162(oh[2], oh[3]);
        *(__nv_bfloat162*)&g_al[base]   = __nv_bfloat162(ol[0], ol[1]);
        *(__nv_bfloat162*)&g_al[base+2] = __nv_bfloat162(ol[2], ol[3]);
    }
}

// ---------------------------------------------------------------------------
extern "C" void kernel_launch(void* const* d_in, const int* in_sizes, int n_in,
                              void* d_out, int out_size)
{
    const float* x     = (const float*)d_in[0];
    const float* w_qkv = (const float*)d_in[1];
    const float* b_qkv = (const float*)d_in[2];
    const float* w_out = (const float*)d_in[3];
    const float* b_out = (const float*)d_in[4];
    float* out = (float*)d_out;

    __nv_bfloat16 *xh, *xl, *wqh, *wql, *woh, *wol, *ah, *al;
    cudaGetSymbolAddress((void**)&xh,  g_xh);
    cudaGetSymbolAddress((void**)&xl,  g_xl);
    cudaGetSymbolAddress((void**)&wqh, g_wqh);
    cudaGetSymbolAddress((void**)&wql, g_wql);
    cudaGetSymbolAddress((void**)&woh, g_woh);
    cudaGetSymbolAddress((void**)&wol, g_wol);
    cudaGetSymbolAddress((void**)&ah,  g_ah);
    cudaGetSymbolAddress((void**)&al,  g_al);

    const int att_smem = ATT_SMEM_FLOATS * (int)sizeof(float);
    cudaFuncSetAttribute(attn_kernel,
                         cudaFuncAttributeMaxDynamicSharedMemorySize, att_smem);
    cudaFuncSetAttribute(gemm_mma<0>,
                         cudaFuncAttributeMaxDynamicSharedMemorySize, GEMM_SMEM);
    cudaFuncSetAttribute(gemm_mma<1>,
                         cudaFuncAttributeMaxDynamicSharedMemorySize, GEMM_SMEM);

    // 1) split x into bf16 hi/lo
    split_kernel<<<MROWS*DM/1024, 256>>>(x, xh, xl);
    // 2) transpose+split weights ([K,N] -> [N,K] hi/lo)
    tsplit_kernel<<<dim3(3*DM/32, DM/32), dim3(32, 8)>>>(w_qkv, wqh, wql, DM, 3*DM);
    tsplit_kernel<<<dim3(DM/32,   DM/32), dim3(32, 8)>>>(w_out, woh, wol, DM, DM);
    // 3) qkv projection (HMMA split-bf16), scattered to [B,H,S,HD]
    gemm_mma<0><<<dim3(3*DM/128, MROWS/128), 256, GEMM_SMEM>>>(
        xh, xl, wqh, wql, b_qkv, nullptr, 3*DM);
    // 4) attention (fp32), writes split bf16 output
    attn_kernel<<<dim3(TS/BR, NB*NH), 256, att_smem>>>();
    // 5) output projection (HMMA split-bf16) -> d_out
    gemm_mma<1><<<dim3(DM/128, MROWS/128), 256, GEMM_SMEM>>>(
        ah, al, woh, wol, b_out, out, DM);
}

// round 4
// speedup vs baseline: 2.9985x; 2.1248x over previous
#include <cuda_runtime.h>
#include <cuda_bf16.h>
#include <cstdint>

#define TS 2048       // sequence length
#define DM 1024       // d_model
#define NH 16         // heads
#define HD 64         // head dim
#define NB 2          // batch
#define MROWS (NB*TS) // 4096
#define GK DM         // reduction dim for projection GEMMs
#define KC 64         // bf16 cols per K-chunk (128 bytes = SW128 row)
#define NCH (GK/KC)   // 16 chunks

// ---------------- scratch (no cudaMalloc allowed) ----------------
static __device__ __align__(256) __nv_bfloat16 g_qh[NB*NH*TS*HD], g_ql[NB*NH*TS*HD];
static __device__ __align__(256) __nv_bfloat16 g_kh[NB*NH*TS*HD], g_kl[NB*NH*TS*HD];
static __device__ __align__(256) __nv_bfloat16 g_vh[NB*NH*TS*HD], g_vl[NB*NH*TS*HD];
static __device__ __align__(256) __nv_bfloat16 g_xh[MROWS*DM],  g_xl[MROWS*DM];   // x split
static __device__ __align__(256) __nv_bfloat16 g_wqh[3*DM*DM],  g_wql[3*DM*DM];   // w_qkv^T split [3D, D]
static __device__ __align__(256) __nv_bfloat16 g_woh[DM*DM],    g_wol[DM*DM];     // w_out^T split [D, D]
static __device__ __align__(256) __nv_bfloat16 g_ah[MROWS*DM],  g_al[MROWS*DM];   // attn output split

// ---------------- helpers ----------------
__device__ __forceinline__ uint32_t smem_u32(const void* p) {
    uint32_t a;
    asm("{ .reg .u64 t; cvta.to.shared.u64 t, %1; cvt.u32.u64 %0, t; }" : "=r"(a) : "l"(p));
    return a;
}
__device__ __forceinline__ void ldsm4(uint32_t* d, uint32_t addr) {
    asm volatile("ldmatrix.sync.aligned.m8n8.x4.shared.b16 {%0,%1,%2,%3}, [%4];"
        : "=r"(d[0]), "=r"(d[1]), "=r"(d[2]), "=r"(d[3]) : "r"(addr));
}
__device__ __forceinline__ void ldsm4t(uint32_t* d, uint32_t addr) {
    asm volatile("ldmatrix.sync.aligned.m8n8.x4.trans.shared.b16 {%0,%1,%2,%3}, [%4];"
        : "=r"(d[0]), "=r"(d[1]), "=r"(d[2]), "=r"(d[3]) : "r"(addr));
}
__device__ __forceinline__ void mma16816(float* c, const uint32_t* a, const uint32_t* b) {
    asm volatile("mma.sync.aligned.m16n8k16.row.col.f32.bf16.bf16.f32 "
        "{%0,%1,%2,%3}, {%4,%5,%6,%7}, {%8,%9}, {%0,%1,%2,%3};"
        : "+f"(c[0]), "+f"(c[1]), "+f"(c[2]), "+f"(c[3])
        : "r"(a[0]), "r"(a[1]), "r"(a[2]), "r"(a[3]), "r"(b[0]), "r"(b[1]));
}
__device__ __forceinline__ void cpasync16(uint32_t dst, const void* src) {
    asm volatile("cp.async.cg.shared.global [%0], [%1], 16;" :: "r"(dst), "l"(src));
}
#define CP_COMMIT() asm volatile("cp.async.commit_group;" ::: "memory")
#define CP_WAIT0()  asm volatile("cp.async.wait_group 0;" ::: "memory")

// pack (f0 -> low half, f1 -> high half) as bf16x2
__device__ __forceinline__ uint32_t pack_bf16x2(float f0, float f1) {
    uint32_t r;
    asm("cvt.rn.bf16x2.f32 %0, %1, %2;" : "=r"(r) : "f"(f1), "f"(f0));
    return r;
}
// split two floats into (hi bf16x2, lo bf16x2)
__device__ __forceinline__ void split2(float f0, float f1, uint32_t& hh, uint32_t& ll) {
    hh = pack_bf16x2(f0, f1);
    float h0 = __uint_as_float(hh << 16);
    float h1 = __uint_as_float(hh & 0xffff0000u);
    ll = pack_bf16x2(f0 - h0, f1 - h1);
}

// ---------------- conversion kernels ----------------
__global__ __launch_bounds__(256)
void split_kernel(const float* __restrict__ s, __nv_bfloat16* __restrict__ h,
                  __nv_bfloat16* __restrict__ l)
{
    int i = (blockIdx.x * 256 + threadIdx.x) * 4;
    float4 v = *(const float4*)(s + i);
    uint32_t h0, l0, h1, l1;
    split2(v.x, v.y, h0, l0);
    split2(v.z, v.w, h1, l1);
    *(uint32_t*)(h + i)     = h0;
    *(uint32_t*)(h + i + 2) = h1;
    *(uint32_t*)(l + i)     = l0;
    *(uint32_t*)(l + i + 2) = l1;
}

// transpose + split: src[K,N] fp32 -> hT/lT[N,K] bf16
__global__ __launch_bounds__(256)
void tsplit_kernel(const float* __restrict__ s, __nv_bfloat16* __restrict__ hT,
                   __nv_bfloat16* __restrict__ lT, int K, int N)
{
    __shared__ float t[32][33];
    const int n0 = blockIdx.x * 32, k0 = blockIdx.y * 32;
    const int tx = threadIdx.x, ty = threadIdx.y;   // (32, 8)
#pragma unroll
    for (int j = 0; j < 4; j++)
        t[ty + j*8][tx] = s[(size_t)(k0 + ty + j*8) * N + n0 + tx];
    __syncthreads();
#pragma unroll
    for (int j = 0; j < 4; j++) {
        float v = t[tx][ty + j*8];
        __nv_bfloat16 h = __float2bfloat16(v);
        __nv_bfloat16 l = __float2bfloat16(v - __bfloat162float(h));
        size_t o = (size_t)(n0 + ty + j*8) * K + k0 + tx;
        hT[o] = h; lT[o] = l;
    }
}

// ---------------- split-bf16 mma.sync GEMM ----------------
// EPI=0: bias (+ Q scale) + split-bf16 scatter to g_{q,k,v}{h,l} [B,H,S,HD]
// EPI=1: bias + fp32 row-major C
#define TILE_B 16384                  // 128 rows x 128 bytes
#define BUF_B  (4 * TILE_B)           // Ah, Al, Bh, Bl
#define GEMM_SMEM (2 * BUF_B)         // 131072 (double buffered)

template <int EPI>
__global__ __launch_bounds__(256)
void gemm_mma(const __nv_bfloat16* __restrict__ Ah,
              const __nv_bfloat16* __restrict__ Al,
              const __nv_bfloat16* __restrict__ Bh,
              const __nv_bfloat16* __restrict__ Bl,
              const float* __restrict__ bias,
              float* __restrict__ C, int Ncols)
{
    extern __shared__ __align__(128) char smc[];
    const uint32_t smb = smem_u32(smc);
    const int tid = threadIdx.x;
    const int lane = tid & 31, wid = tid >> 5;
    const int m0 = blockIdx.y * 128;
    const int n0 = blockIdx.x * 128;
    const int wm = (wid & 3) * 32;
    const int wn = (wid >> 2) * 64;

    float acc[2][8][4];
#pragma unroll
    for (int mf = 0; mf < 2; mf++)
#pragma unroll
        for (int nf = 0; nf < 8; nf++)
#pragma unroll
            for (int j = 0; j < 4; j++) acc[mf][nf][j] = 0.f;

    const __nv_bfloat16* srcs[4] = {Ah, Al, Bh, Bl};

    auto load_chunk = [&](int c, int stage) {
#pragma unroll
        for (int t = 0; t < 4; t++) {
            const int rowbase = (t < 2) ? m0 : n0;
            const __nv_bfloat16* g = srcs[t] + (size_t)rowbase * GK + c * KC;
            const uint32_t sbase = smb + stage * BUF_B + t * TILE_B;
#pragma unroll
            for (int i = 0; i < 4; i++) {
                const int idx = tid + i * 256;
                const int r = idx >> 3;
                const int c8 = (idx & 7) << 3;
                uint32_t off = r * 128 + c8 * 2;
                uint32_t sw = off ^ ((off >> 3) & 0x70);
                cpasync16(sbase + sw, g + (size_t)r * GK + c8);
            }
        }
        CP_COMMIT();
    };

    load_chunk(0, 0);

    const uint32_t a_row  = wm + (lane & 15);
    const uint32_t a_koff = (lane >> 4) * 16;
    const uint32_t b_row  = wn + ((lane >> 4) << 3) + (lane & 7);
    const uint32_t b_koff = ((lane >> 3) & 1) * 16;

    for (int c = 0; c < NCH; ++c) {
        const int st = c & 1;
        CP_WAIT0();
        __syncthreads();
        if (c + 1 < NCH) load_chunk(c + 1, st ^ 1);

        const uint32_t base = smb + st * BUF_B;
#pragma unroll
        for (int ks = 0; ks < 4; ks++) {
            const uint32_t kb = ks * 32;
            uint32_t ah[2][4], al[2][4], bh[4][4], bl[4][4];
#pragma unroll
            for (int mf = 0; mf < 2; mf++) {
                uint32_t off = (a_row + mf * 16) * 128 + kb + a_koff;
                uint32_t sw = off ^ ((off >> 3) & 0x70);
                ldsm4(ah[mf], base + sw);
                ldsm4(al[mf], base + TILE_B + sw);
            }
#pragma unroll
            for (int nf2 = 0; nf2 < 4; nf2++) {
                uint32_t off = (b_row + nf2 * 16) * 128 + kb + b_koff;
                uint32_t sw = off ^ ((off >> 3) & 0x70);
                ldsm4(bh[nf2], base + 2 * TILE_B + sw);
                ldsm4(bl[nf2], base + 3 * TILE_B + sw);
            }
#pragma unroll
            for (int mf = 0; mf < 2; mf++)
#pragma unroll
                for (int nf = 0; nf < 8; nf++) {
                    const uint32_t* bhp = &bh[nf >> 1][(nf & 1) * 2];
                    const uint32_t* blp = &bl[nf >> 1][(nf & 1) * 2];
                    mma16816(acc[mf][nf], ah[mf], bhp);
                    mma16816(acc[mf][nf], ah[mf], blp);
                    mma16816(acc[mf][nf], al[mf], bhp);
                }
        }
    }

    // ---- epilogue ----
#pragma unroll
    for (int mf = 0; mf < 2; mf++) {
#pragma unroll
        for (int nf = 0; nf < 8; nf++) {
            const int n = n0 + wn + nf * 8 + (lane & 3) * 2;
            const int row0 = m0 + wm + mf * 16 + (lane >> 2);
            const float2 bb = *(const float2*)&bias[n];
            if (EPI == 0) {
                const int which = n >> 10;           // 0=q,1=k,2=v
                const int h = (n >> 6) & 15;
                const int hd = n & 63;
                const float scl = (which == 0) ? 0.125f : 1.0f;
                __nv_bfloat16* dh = (which == 0) ? g_qh : (which == 1) ? g_kh : g_vh;
                __nv_bfloat16* dl = (which == 0) ? g_ql : (which == 1) ? g_kl : g_vl;
#pragma unroll
                for (int rr = 0; rr < 2; rr++) {
                    const int row = row0 + rr * 8;
                    const int bi = row >> 11;        // / TS
                    const int s = row & (TS - 1);
                    float f0 = (acc[mf][nf][rr*2+0] + bb.x) * scl;
                    float f1 = (acc[mf][nf][rr*2+1] + bb.y) * scl;
                    uint32_t hh, ll;
                    split2(f0, f1, hh, ll);
                    const size_t o = ((size_t)(bi * NH + h) * TS + s) * HD + hd;
                    *(uint32_t*)&dh[o] = hh;
                    *(uint32_t*)&dl[o] = ll;
                }
            } else {
#pragma unroll
                for (int rr = 0; rr < 2; rr++) {
                    const int row = row0 + rr * 8;
                    float2 v;
                    v.x = acc[mf][nf][rr*2+0] + bb.x;
                    v.y = acc[mf][nf][rr*2+1] + bb.y;
                    *(float2*)&C[(size_t)row * Ncols + n] = v;
                }
            }
        }
    }
}

// ---------------------------------------------------------------------------
// Flash attention via mma.sync, split-bf16 on both contractions.
// CTA: 128 q-rows of one (b,h). 8 warps x 16 rows. Bc = 64.
// smem: Qh[128][64] @0, Ql @16384; stages @32768 + st*32768:
//       Kh +0, Kl +8192, Vh +16384, Vl +24576 (each 64x64 bf16, SW128)
// ---------------------------------------------------------------------------
#define ABR 128
#define ABC 64
#define NKT (TS/ABC)          // 32 chunks
#define ATT_SMEM (32768 + 2*32768)

__global__ __launch_bounds__(256)
void attn_mma_kernel()
{
    extern __shared__ __align__(128) char smc[];
    const uint32_t smb = smem_u32(smc);
    const int tid = threadIdx.x, lane = tid & 31, wid = tid >> 5;
    const int bh = blockIdx.y;
    const int q0 = blockIdx.x * ABR;
    const int wm = wid * 16;

    const size_t hb = (size_t)bh * TS * HD;
    const char* Qhg = (const char*)(g_qh + hb + (size_t)q0 * HD);
    const char* Qlg = (const char*)(g_ql + hb + (size_t)q0 * HD);
    const char* kvg[4] = {(const char*)(g_kh + hb), (const char*)(g_kl + hb),
                          (const char*)(g_vh + hb), (const char*)(g_vl + hb)};

    // load Q hi/lo (128 rows x 128B each)
#pragma unroll
    for (int i = 0; i < 4; i++) {
        const int idx = tid + i * 256;          // [0,1024)
        const int r = idx >> 3;
        const int c8 = (idx & 7) * 16;          // byte col
        uint32_t off = r * 128 + c8;
        uint32_t sw = off ^ ((off >> 3) & 0x70);
        cpasync16(smb + sw, Qhg + (size_t)r * 128 + c8);
        cpasync16(smb + 16384 + sw, Qlg + (size_t)r * 128 + c8);
    }
    CP_COMMIT();

    auto load_kv = [&](int kt, int st) {
        const uint32_t sb = smb + 32768 + st * 32768;
        const size_t gofs = (size_t)kt * ABC * HD * 2;   // bytes
#pragma unroll
        for (int t = 0; t < 4; t++) {
            const char* g = kvg[t] + gofs;
#pragma unroll
            for (int i = 0; i < 2; i++) {
                const int idx = tid + i * 256;  // [0,512)
                const int r = idx >> 3;
                const int c8 = (idx & 7) * 16;
                uint32_t off = r * 128 + c8;
                uint32_t sw = off ^ ((off >> 3) & 0x70);
                cpasync16(sb + t * 8192 + sw, g + (size_t)r * 128 + c8);
            }
        }
        CP_COMMIT();
    };
    load_kv(0, 0);

    const uint32_t a_row  = wm + (lane & 15);
    const uint32_t a_koff = (lane >> 4) * 16;
    const uint32_t b_row  = ((lane >> 4) << 3) + (lane & 7);
    const uint32_t b_koff = ((lane >> 3) & 1) * 16;
    // V trans-ldmatrix per-lane offsets
    const int vg_g = lane >> 3, vg_r = lane & 7;

    float m0r = -1e30f, m1r = -1e30f, l0 = 0.f, l1 = 0.f;
    float oacc[8][4];
#pragma unroll
    for (int nf = 0; nf < 8; nf++)
#pragma unroll
        for (int j = 0; j < 4; j++) oacc[nf][j] = 0.f;

    for (int kt = 0; kt < NKT; ++kt) {
        const int st = kt & 1;
        CP_WAIT0();
        __syncthreads();
        if (kt + 1 < NKT) load_kv(kt + 1, st ^ 1);

        const uint32_t kvb = smb + 32768 + st * 32768;

        // ---- S = Q K^T (128x64, split 3-mma) ----
        float sacc[8][4];
#pragma unroll
        for (int nf = 0; nf < 8; nf++)
#pragma unroll
            for (int j = 0; j < 4; j++) sacc[nf][j] = 0.f;

#pragma unroll
        for (int ks = 0; ks < 4; ks++) {
            const uint32_t kb = ks * 32;
            uint32_t qh[4], ql[4];
            {
                uint32_t off = a_row * 128 + kb + a_koff;
                uint32_t sw = off ^ ((off >> 3) & 0x70);
                ldsm4(qh, smb + sw);
                ldsm4(ql, smb + 16384 + sw);
            }
#pragma unroll
            for (int nf2 = 0; nf2 < 4; nf2++) {
                uint32_t kh[4], kl[4];
                uint32_t off = (b_row + nf2 * 16) * 128 + kb + b_koff;
                uint32_t sw = off ^ ((off >> 3) & 0x70);
                ldsm4(kh, kvb + sw);
                ldsm4(kl, kvb + 8192 + sw);
#pragma unroll
                for (int half = 0; half < 2; half++) {
                    const int nf = nf2 * 2 + half;
                    mma16816(sacc[nf], qh, &kh[half * 2]);
                    mma16816(sacc[nf], qh, &kl[half * 2]);
                    mma16816(sacc[nf], ql, &kh[half * 2]);
                }
            }
        }

        // ---- online softmax (thread rows: r0 = lane>>2, r1 = r0+8) ----
        float mr0 = -1e30f, mr1 = -1e30f;
#pragma unroll
        for (int nf = 0; nf < 8; nf++) {
            mr0 = fmaxf(mr0, fmaxf(sacc[nf][0], sacc[nf][1]));
            mr1 = fmaxf(mr1, fmaxf(sacc[nf][2], sacc[nf][3]));
        }
        mr0 = fmaxf(mr0, __shfl_xor_sync(0xffffffffu, mr0, 1));
        mr0 = fmaxf(mr0, __shfl_xor_sync(0xffffffffu, mr0, 2));
        mr1 = fmaxf(mr1, __shfl_xor_sync(0xffffffffu, mr1, 1));
        mr1 = fmaxf(mr1, __shfl_xor_sync(0xffffffffu, mr1, 2));
        const float mn0 = fmaxf(m0r, mr0);
        const float mn1 = fmaxf(m1r, mr1);
        const float al0 = __expf(m0r - mn0);
        const float al1 = __expf(m1r - mn1);
        m0r = mn0; m1r = mn1;

        float s0 = 0.f, s1 = 0.f;
        uint32_t ph[4][4], pl[4][4];
#pragma unroll
        for (int nf = 0; nf < 8; nf++) {
            float p0 = __expf(sacc[nf][0] - mn0);
            float p1 = __expf(sacc[nf][1] - mn0);
            float p2 = __expf(sacc[nf][2] - mn1);
            float p3 = __expf(sacc[nf][3] - mn1);
            s0 += p0 + p1; s1 += p2 + p3;
            const int kf = nf >> 1, hi2 = (nf & 1) * 2;
            uint32_t hA, lA, hB, lB;
            split2(p0, p1, hA, lA);
            split2(p2, p3, hB, lB);
            ph[kf][hi2 + 0] = hA; ph[kf][hi2 + 1] = hB;
            pl[kf][hi2 + 0] = lA; pl[kf][hi2 + 1] = lB;
        }
        s0 += __shfl_xor_sync(0xffffffffu, s0, 1);
        s0 += __shfl_xor_sync(0xffffffffu, s0, 2);
        s1 += __shfl_xor_sync(0xffffffffu, s1, 1);
        s1 += __shfl_xor_sync(0xffffffffu, s1, 2);
        l0 = l0 * al0 + s0;
        l1 = l1 * al1 + s1;
#pragma unroll
        for (int nf = 0; nf < 8; nf++) {
            oacc[nf][0] *= al0; oacc[nf][1] *= al0;
            oacc[nf][2] *= al1; oacc[nf][3] *= al1;
        }

        // wait: ph frag layout note — a0=(nf even c0c1), a1=(nf even c2c3),
        // a2=(nf odd c0c1), a3=(nf odd c2c3). Stored above as [hi2+0]=even pair?
        // hi2: nf even -> slots 0,1 = (c0c1, c2c3); nf odd -> slots 2,3. Correct.

        // ---- O += P V (split 3-mma), V via ldmatrix.trans ----
#pragma unroll
        for (int kf = 0; kf < 4; kf++) {
#pragma unroll
            for (int vg = 0; vg < 4; vg++) {     // hd group of 16
                uint32_t vh[4], vl[4];
                uint32_t off = (kf * 16 + (vg_g & 1) * 8 + vg_r) * 128
                             + (vg * 16 + (vg_g >> 1) * 8) * 2;
                uint32_t sw = off ^ ((off >> 3) & 0x70);
                ldsm4t(vh, kvb + 16384 + sw);
                ldsm4t(vl, kvb + 24576 + sw);
#pragma unroll
                for (int half = 0; half < 2; half++) {
                    const int nfo = vg * 2 + half;
                    mma16816(oacc[nfo], ph[kf], &vh[half * 2]);
                    mma16816(oacc[nfo], ph[kf], &vl[half * 2]);
                    mma16816(oacc[nfo], pl[kf], &vh[half * 2]);
                }
            }
        }
    }

    // ---- epilogue: normalize, split bf16, write [B,S,D] ----
    const int b = bh >> 4;
    const int h = bh & 15;
    const float inv0 = 1.0f / l0;
    const float inv1 = 1.0f / l1;
    const int row0 = q0 + wm + (lane >> 2);
#pragma unroll
    for (int nf = 0; nf < 8; nf++) {
        const int hd = nf * 8 + (lane & 3) * 2;
        const size_t o0 = ((size_t)(b * TS + row0)) * DM + h * HD + hd;
        const size_t o1 = o0 + (size_t)8 * DM;
        uint32_t hh, ll;
        split2(oacc[nf][0] * inv0, oacc[nf][1] * inv0, hh, ll);
        *(uint32_t*)&g_ah[o0] = hh;
        *(uint32_t*)&g_al[o0] = ll;
        split2(oacc[nf][2] * inv1, oacc[nf][3] * inv1, hh, ll);
        *(uint32_t*)&g_ah[o1] = hh;
        *(uint32_t*)&g_al[o1] = ll;
    }
}

// ---------------------------------------------------------------------------
extern "C" void kernel_launch(void* const* d_in, const int* in_sizes, int n_in,
                              void* d_out, int out_size)
{
    const float* x     = (const float*)d_in[0];
    const float* w_qkv = (const float*)d_in[1];
    const float* b_qkv = (const float*)d_in[2];
    const float* w_out = (const float*)d_in[3];
    const float* b_out = (const float*)d_in[4];
    float* out = (float*)d_out;

    __nv_bfloat16 *xh, *xl, *wqh, *wql, *woh, *wol, *ah, *al;
    cudaGetSymbolAddress((void**)&xh,  g_xh);
    cudaGetSymbolAddress((void**)&xl,  g_xl);
    cudaGetSymbolAddress((void**)&wqh, g_wqh);
    cudaGetSymbolAddress((void**)&wql, g_wql);
    cudaGetSymbolAddress((void**)&woh, g_woh);
    cudaGetSymbolAddress((void**)&wol, g_wol);
    cudaGetSymbolAddress((void**)&ah,  g_ah);
    cudaGetSymbolAddress((void**)&al,  g_al);

    cudaFuncSetAttribute(gemm_mma<0>,
                         cudaFuncAttributeMaxDynamicSharedMemorySize, GEMM_SMEM);
    cudaFuncSetAttribute(gemm_mma<1>,
                         cudaFuncAttributeMaxDynamicSharedMemorySize, GEMM_SMEM);
    cudaFuncSetAttribute(attn_mma_kernel,
                         cudaFuncAttributeMaxDynamicSharedMemorySize, ATT_SMEM);

    // 1) split x into bf16 hi/lo
    split_kernel<<<MROWS*DM/1024, 256>>>(x, xh, xl);
    // 2) transpose+split weights ([K,N] -> [N,K] hi/lo)
    tsplit_kernel<<<dim3(3*DM/32, DM/32), dim3(32, 8)>>>(w_qkv, wqh, wql, DM, 3*DM);
    tsplit_kernel<<<dim3(DM/32,   DM/32), dim3(32, 8)>>>(w_out, woh, wol, DM, DM);
    // 3) qkv projection -> split bf16 Q(scaled)/K/V in [B,H,S,HD]
    gemm_mma<0><<<dim3(3*DM/128, MROWS/128), 256, GEMM_SMEM>>>(
        xh, xl, wqh, wql, b_qkv, nullptr, 3*DM);
    // 4) attention (HMMA split-bf16) -> split bf16 [B,S,D]
    attn_mma_kernel<<<dim3(TS/ABR, NB*NH), 256, ATT_SMEM>>>();
    // 5) output projection -> d_out
    gemm_mma<1><<<dim3(DM/128, MROWS/128), 256, GEMM_SMEM>>>(
        ah, al, woh, wol, b_out, out, DM);
}